// round 15
// baseline (speedup 1.0000x reference)
#include <cuda_runtime.h>
#include <cuda_fp16.h>

#define NSEQ 12800
#define TSTEPS 512
#define CHUNK_T 4
#define NCHUNK (TSTEPS / CHUNK_T)
#define RING 4
#define ROWB 48                      // padded fp16 x-tile row (bytes, 16-aligned, bank-distinct)
#define TILE_B (16 * ROWB)           // 768 B per 16x(K) fp16 tile
#define GRS 26                       // gate smem row stride (words)
#define G_B (16 * GRS * 4)           // 1664 B gate buffer
#define WARP_SMEM (RING * TILE_B + G_B)   // 4736 B per warp

typedef unsigned long long u64;

// ---------- packed f32x2 + fast-math helpers ----------
__device__ __forceinline__ u64 pk2(float lo, float hi) {
    u64 u; asm("mov.b64 %0, {%1,%2};" : "=l"(u) : "f"(lo), "f"(hi)); return u;
}
__device__ __forceinline__ float2 upk2(u64 u) {
    float2 v; asm("mov.b64 {%0,%1}, %2;" : "=f"(v.x), "=f"(v.y) : "l"(u)); return v;
}
__device__ __forceinline__ u64 ffma2(u64 a, u64 b, u64 c) {
    u64 d; asm("fma.rn.f32x2 %0, %1, %2, %3;" : "=l"(d) : "l"(a), "l"(b), "l"(c)); return d;
}
__device__ __forceinline__ float tanh_a(float x) {
    float r; asm("tanh.approx.f32 %0, %1;" : "=f"(r) : "f"(x)); return r;
}
__device__ __forceinline__ float hsum(u64 a) { float2 v = upk2(a); return v.x + v.y; }

// sigmoid(y) = 0.5*tanh(0.5*y) + 0.5 ; the 0.5 factor is pre-folded into the
// r/z weights and biases (both x-side, via MMA B/C fragments, and h-side).
#define KRZ (0.5f)

// ---------- global scratch ----------
// Per-DIRECTION fp16 activation buffers, layout (T, N, 8): a warp's 32 lanes
// store 64 contiguous bytes per step (2 full sectors, no read-modify-write).
__device__ unsigned short g_F0[(size_t)TSTEPS * NSEQ * 8];
__device__ unsigned short g_B0[(size_t)TSTEPS * NSEQ * 8];
__device__ unsigned short g_F1[(size_t)TSTEPS * NSEQ * 8];
__device__ unsigned short g_B1[(size_t)TSTEPS * NSEQ * 8];
__device__ unsigned short g_rawH[(size_t)NSEQ * TSTEPS * 8];

// ---------- raw fp32 -> fp16 convert pre-pass ----------
__global__ void __launch_bounds__(256) cvt_kernel(const float4* __restrict__ in,
                                                  uint2* __restrict__ outp) {
    int i = blockIdx.x * blockDim.x + threadIdx.x;
    float4 v = in[i];
    __half2 h0 = __floats2half2_rn(v.x, v.y);
    __half2 h1 = __floats2half2_rn(v.z, v.w);
    outp[i] = make_uint2(*(unsigned*)&h0, *(unsigned*)&h1);
}

// ---------- per-WARP cp.async x-tile loader ----------
// One 16-row fp16 tile per chunk: row r = (step-in-chunk)*4 + scan.
// Row layout: [fwd-x 8 halves | bwd-x 8 halves] (hsel picks source buffer).
template <int INF, bool L0IN>
__device__ __forceinline__ void issue_chunk(unsigned dst_s,
                                            const __half* __restrict__ xF,
                                            const __half* __restrict__ xB,
                                            int n0, int c, int dir, int lane) {
    int r, hsel; bool pred;
    if (INF == 16) { r = lane >> 1; hsel = lane & 1; pred = true; }
    else           { r = lane & 15; hsel = 0;        pred = lane < 16; }
    int s = c * CHUNK_T + (r >> 2);
    int scan = r & 3;
    int t = dir ? (TSTEPS - 1 - s) : s;
    const __half* g = L0IN
        ? xF + ((size_t)(n0 + scan) * TSTEPS + t) * 8
        : (hsel ? xB : xF) + ((size_t)t * NSEQ + (n0 + scan)) * 8;
    unsigned d = dst_s + r * ROWB + hsel * 16;
    if (pred)
        asm volatile("cp.async.cg.shared.global [%0], [%1], 16;" :: "r"(d), "l"(g));
}

// One bidirectional-GRU layer. Each WARP owns 4 scans of one direction.
// x-projection on TENSOR CORES (mma.m16n8k{16,8}, fp16 in, fp32 accumulate,
// bias in C); D fragments transpose to recurrence lanes via a bank-padded
// smem gate buffer. h-recurrence + gates stay fp32. Inter-layer activations
// fp16 in per-direction (T,N,8) buffers (coalesced 64B warp stores).
// HEAD (layer 3): fwd only, no stores; fused 1-step bwd GRU at t=T-1 (h0=0)
// + lin1/LeakyReLU(0.2)/lin2 head (fp32).
template <int INF, bool L0IN, bool HEAD>
__global__ void __launch_bounds__(128, 4)
gru_layer_kernel(const __half* __restrict__ xF, const __half* __restrict__ xB,
                 __half* __restrict__ outF, __half* __restrict__ outB,
                 const float* __restrict__ Wih, const float* __restrict__ Whh,
                 const float* __restrict__ bih, const float* __restrict__ bhh,
                 int wih_stride,
                 const float* __restrict__ l1w, const float* __restrict__ l1b,
                 const float* __restrict__ l2w, const float* __restrict__ l2b,
                 float* __restrict__ out)
{
    extern __shared__ char sb[];

    const int tid = threadIdx.x;
    const int wid = tid >> 5;
    const int lane = tid & 31;
    const int u = tid & 7;
    const int sg = (tid >> 3) & 3;               // scan within warp
    const int warpG = blockIdx.x * 4 + wid;
    const int dir = HEAD ? 0 : (warpG / (NSEQ / 4));
    const int wi  = HEAD ? warpG : (warpG % (NSEQ / 4));
    const int n0 = wi * 4;
    const int n = n0 + sg;

    char* wsb = sb + wid * WARP_SMEM;            // warp-private region
    char* gsm = wsb + RING * TILE_B;             // gate buffer (fp32)
    const unsigned wsb_s = (unsigned)__cvta_generic_to_shared(wsb);
    float* gw = reinterpret_cast<float*>(gsm);

    const float* wih = Wih + dir * wih_stride;
    const float* whh = Whh + dir * 192;
    const float* bi  = bih + dir * 24;
    const float* bh  = bhh + dir * 24;

    // ---- B fragments (x-projection weights, fp16, pre-scaled) ----
    const int bg = lane >> 2;                    // n-within-tile
    const int bt = lane & 3;                     // k-pair index
    unsigned bfr[6];
#pragma unroll
    for (int j = 0; j < 3; j++) {
        int m = j * 8 + bg;
        float sc = (m < 16) ? KRZ : 1.0f;
        const float* wrow = wih + m * INF + 2 * bt;
        __half2 h0 = __floats2half2_rn(sc * wrow[0], sc * wrow[1]);
        if (INF == 16) {
            __half2 h1 = __floats2half2_rn(sc * wrow[8], sc * wrow[9]);
            bfr[2 * j]     = *(unsigned*)&h0;
            bfr[2 * j + 1] = *(unsigned*)&h1;
        } else {
            bfr[j] = *(unsigned*)&h0;            // k8 path uses bfr[j]
        }
    }
    // C-fragment biases (per-column): r/z cols get 0.5*(bi+bh); n cols bi only.
    float cb0[3], cb1[3];
#pragma unroll
    for (int j = 0; j < 3; j++) {
        int c0 = j * 8 + 2 * bt;
        cb0[j] = (c0     < 16) ? KRZ * (bi[c0]     + bh[c0])     : bi[c0];
        cb1[j] = (c0 + 1 < 16) ? KRZ * (bi[c0 + 1] + bh[c0 + 1]) : bi[c0 + 1];
    }

    // ---- h-recurrence weights (fp32 packed, pre-scaled) ----
    u64 ur[4], uz[4], un[4];
#pragma unroll
    for (int p = 0; p < 4; p++) {
        ur[p] = pk2(KRZ * whh[(u     ) * 8 + 2 * p], KRZ * whh[(u     ) * 8 + 2 * p + 1]);
        uz[p] = pk2(KRZ * whh[(u +  8) * 8 + 2 * p], KRZ * whh[(u +  8) * 8 + 2 * p + 1]);
        un[p] = pk2(       whh[(u + 16) * 8 + 2 * p],        whh[(u + 16) * 8 + 2 * p + 1]);
    }
    const u64 bnhp = pk2(bh[u + 16], 0.0f);

    const int t0 = dir ? (TSTEPS - 1) : 0;
    __half* op = HEAD ? nullptr
                      : ((dir ? outB : outF) + ((size_t)t0 * NSEQ + (size_t)n) * 8 + u);
    const ptrdiff_t ostep = (ptrdiff_t)NSEQ * 8 * (dir ? -1 : 1);

    // ---- prime the x pipeline (3 chunks in flight) ----
    issue_chunk<INF, L0IN>(wsb_s + 0 * TILE_B, xF, xB, n0, 0, dir, lane);
    asm volatile("cp.async.commit_group;" ::: "memory");
    issue_chunk<INF, L0IN>(wsb_s + 1 * TILE_B, xF, xB, n0, 1, dir, lane);
    asm volatile("cp.async.commit_group;" ::: "memory");
    issue_chunk<INF, L0IN>(wsb_s + 2 * TILE_B, xF, xB, n0, 2, dir, lane);
    asm volatile("cp.async.commit_group;" ::: "memory");

    float h = 0.0f;
    const int dg = lane >> 2;                    // D-frag row group
    const int dcol = 2 * (lane & 3);             // D-frag col pair base

#pragma unroll 1
    for (int c = 0; c < NCHUNK; c++) {
        asm volatile("cp.async.wait_group 2;" ::: "memory");
        __syncwarp();
        const unsigned tile_s = wsb_s + (c & (RING - 1)) * TILE_B;

        // ---- MMA phase: x-projection for 4 steps x 4 scans ----
        unsigned a0, a1, a2, a3;
        if (INF == 16) {
            unsigned la = tile_s + (lane & 15) * ROWB + (lane >> 4) * 16;
            asm volatile("ldmatrix.sync.aligned.m8n8.x4.shared.b16 {%0,%1,%2,%3}, [%4];"
                         : "=r"(a0), "=r"(a1), "=r"(a2), "=r"(a3) : "r"(la));
        } else {
            unsigned la = tile_s + (lane & 15) * ROWB;
            asm volatile("ldmatrix.sync.aligned.m8n8.x2.shared.b16 {%0,%1}, [%2];"
                         : "=r"(a0), "=r"(a1) : "r"(la));
        }
#pragma unroll
        for (int j = 0; j < 3; j++) {
            float d0 = cb0[j], d1 = cb1[j], d2 = cb0[j], d3 = cb1[j];
            if (INF == 16)
                asm("mma.sync.aligned.m16n8k16.row.col.f32.f16.f16.f32 "
                    "{%0,%1,%2,%3}, {%4,%5,%6,%7}, {%8,%9}, {%0,%1,%2,%3};"
                    : "+f"(d0), "+f"(d1), "+f"(d2), "+f"(d3)
                    : "r"(a0), "r"(a1), "r"(a2), "r"(a3),
                      "r"(bfr[2 * j]), "r"(bfr[2 * j + 1]));
            else
                asm("mma.sync.aligned.m16n8k8.row.col.f32.f16.f16.f32 "
                    "{%0,%1,%2,%3}, {%4,%5}, {%6}, {%0,%1,%2,%3};"
                    : "+f"(d0), "+f"(d1), "+f"(d2), "+f"(d3)
                    : "r"(a0), "r"(a1), "r"(bfr[j]));
            int col = j * 8 + dcol;
            *(float2*)(gw + dg * GRS + col)       = make_float2(d0, d1);
            *(float2*)(gw + (dg + 8) * GRS + col) = make_float2(d2, d3);
        }
        __syncwarp();

        // ---- recurrence: 4 steps ----
#pragma unroll
        for (int tt = 0; tt < CHUNK_T; tt++) {
            const int grow = (tt * 4 + sg) * GRS;
            float gr = gw[grow + u];             // 0.5*(Wr x + br_i + br_h)
            float gz = gw[grow + 8 + u];
            float gn = gw[grow + 16 + u];        // Wn x + bn_i

            u64 hp[4];
#pragma unroll
            for (int p = 0; p < 4; p++) {
                float lo = __shfl_sync(0xffffffffu, h, 2 * p,     8);
                float hi = __shfl_sync(0xffffffffu, h, 2 * p + 1, 8);
                hp[p] = pk2(lo, hi);
            }
            u64 ar = 0ULL, az = 0ULL, ahn = bnhp;
#pragma unroll
            for (int p = 0; p < 4; p++) {
                ar  = ffma2(ur[p], hp[p], ar);
                az  = ffma2(uz[p], hp[p], az);
                ahn = ffma2(un[p], hp[p], ahn);
            }
            float sr = gr + hsum(ar);
            float sz = gz + hsum(az);
            float shn = hsum(ahn);
            float r = fmaf(0.5f, tanh_a(sr), 0.5f);   // sigmoid
            float z = fmaf(0.5f, tanh_a(sz), 0.5f);   // sigmoid
            float nn = tanh_a(fmaf(r, shn, gn));
            h = fmaf(z, h - nn, nn);

            if (!HEAD) { *op = __float2half_rn(h); op += ostep; }
        }

        if (c + 3 < NCHUNK)
            issue_chunk<INF, L0IN>(wsb_s + ((c + 3) & (RING - 1)) * TILE_B,
                                   xF, xB, n0, c + 3, dir, lane);
        asm volatile("cp.async.commit_group;" ::: "memory");
    }

    if (HEAD) {
        // x[T-1] fp16 still resident: last chunk's tile, row 12+sg.
        const __half2* xh = (const __half2*)(wsb + ((NCHUNK - 1) & (RING - 1)) * TILE_B
                                             + (12 + sg) * ROWB);
        u64 xcp[8];
#pragma unroll
        for (int p = 0; p < 8; p++) {
            float2 f = __half22float2(xh[p]);
            xcp[p] = pk2(f.x, f.y);
        }
        // backward-direction single step at t=T-1, h0=0 (gh = b_hh); fp32.
        const float* wihB = Wih + wih_stride;
        const float* biB  = bih + 24;
        const float* bhB  = bhh + 24;
        u64 br2 = pk2(KRZ * (biB[u]     + bhB[u]),     0.0f);
        u64 bz2 = pk2(KRZ * (biB[u + 8] + bhB[u + 8]), 0.0f);
        u64 bx2 = pk2(biB[u + 16], 0.0f);
        const float bnhB = bhB[u + 16];
#pragma unroll
        for (int p = 0; p < 8; p++) {
            u64 wrB = pk2(KRZ * wihB[(u     ) * 16 + 2 * p], KRZ * wihB[(u     ) * 16 + 2 * p + 1]);
            u64 wzB = pk2(KRZ * wihB[(u +  8) * 16 + 2 * p], KRZ * wihB[(u +  8) * 16 + 2 * p + 1]);
            u64 wnB = pk2(       wihB[(u + 16) * 16 + 2 * p],        wihB[(u + 16) * 16 + 2 * p + 1]);
            br2 = ffma2(wrB, xcp[p], br2);
            bz2 = ffma2(wzB, xcp[p], bz2);
            bx2 = ffma2(wnB, xcp[p], bx2);
        }
        float r = fmaf(0.5f, tanh_a(hsum(br2)), 0.5f);
        float z = fmaf(0.5f, tanh_a(hsum(bz2)), 0.5f);
        float nn = tanh_a(fmaf(r, bnhB, hsum(bx2)));
        float hb = (1.0f - z) * nn;   // h0 = 0

        // head: lin1 + LeakyReLU(0.2) + lin2 over [h_f ; h_b]
        float mid = l1b[u];
#pragma unroll
        for (int cc = 0; cc < 8; cc++) {
            float hf_c = __shfl_sync(0xffffffffu, h,  cc, 8);
            float hb_c = __shfl_sync(0xffffffffu, hb, cc, 8);
            mid = fmaf(l1w[u * 16 + cc],     hf_c, mid);
            mid = fmaf(l1w[u * 16 + 8 + cc], hb_c, mid);
        }
        float act = (mid >= 0.0f) ? mid : 0.2f * mid;

        float o = l2b[u];
#pragma unroll
        for (int cc = 0; cc < 8; cc++) {
            float a_c = __shfl_sync(0xffffffffu, act, cc, 8);
            o = fmaf(l2w[u * 8 + cc], a_c, o);
        }
        out[(size_t)n * 8 + u] = o;
    }
}

extern "C" void kernel_launch(void* const* d_in, const int* in_sizes, int n_in,
                              void* d_out, int out_size) {
    (void)in_sizes; (void)n_in; (void)out_size;
    const float* raw  = (const float*)d_in[0];
    const float* Wih0 = (const float*)d_in[1];
    const float* Whh0 = (const float*)d_in[2];
    const float* bih0 = (const float*)d_in[3];
    const float* bhh0 = (const float*)d_in[4];
    const float* WihR = (const float*)d_in[5];   // (3, 2, 24, 16)
    const float* WhhR = (const float*)d_in[6];   // (3, 2, 24, 8)
    const float* bihR = (const float*)d_in[7];   // (3, 2, 24)
    const float* bhhR = (const float*)d_in[8];   // (3, 2, 24)
    const float* l1w  = (const float*)d_in[9];
    const float* l1b  = (const float*)d_in[10];
    const float* l2w  = (const float*)d_in[11];
    const float* l2b  = (const float*)d_in[12];
    float* out = (float*)d_out;

    __half *F0, *B0, *F1, *B1, *rawH;
    cudaGetSymbolAddress((void**)&F0, g_F0);
    cudaGetSymbolAddress((void**)&B0, g_B0);
    cudaGetSymbolAddress((void**)&F1, g_F1);
    cudaGetSymbolAddress((void**)&B1, g_B1);
    cudaGetSymbolAddress((void**)&rawH, g_rawH);

    const int BLK_FULL = 2 * (NSEQ / 16);   // 1600 blocks (fwd + bwd)
    const int BLK_HEAD = NSEQ / 16;         // 800 blocks (fwd only)
    const int SMEM = 4 * WARP_SMEM;         // 18944 B

    // Pre-pass: raw fp32 -> fp16 (N, T, 8)
    cvt_kernel<<<(NSEQ * TSTEPS * 8) / (256 * 4), 256>>>(
        (const float4*)raw, (uint2*)rawH);

    // Layer 0: rawH -> (F0, B0)  (K=8 MMA)
    gru_layer_kernel<8, true, false><<<BLK_FULL, 128, SMEM>>>(
        rawH, rawH, F0, B0, Wih0, Whh0, bih0, bhh0, 192,
        nullptr, nullptr, nullptr, nullptr, nullptr);

    // Layer 1: (F0, B0) -> (F1, B1)
    gru_layer_kernel<16, false, false><<<BLK_FULL, 128, SMEM>>>(
        F0, B0, F1, B1, WihR + 0 * 768, WhhR + 0 * 384, bihR + 0 * 48, bhhR + 0 * 48, 384,
        nullptr, nullptr, nullptr, nullptr, nullptr);

    // Layer 2: (F1, B1) -> (F0, B0)
    gru_layer_kernel<16, false, false><<<BLK_FULL, 128, SMEM>>>(
        F1, B1, F0, B0, WihR + 1 * 768, WhhR + 1 * 384, bihR + 1 * 48, bhhR + 1 * 48, 384,
        nullptr, nullptr, nullptr, nullptr, nullptr);

    // Layer 3 + head: (F0, B0) -> out
    gru_layer_kernel<16, false, true><<<BLK_HEAD, 128, SMEM>>>(
        F0, B0, nullptr, nullptr, WihR + 2 * 768, WhhR + 2 * 384, bihR + 2 * 48, bhhR + 2 * 48, 384,
        l1w, l1b, l2w, l2b, out);
}

// round 16
// speedup vs baseline: 1.0174x; 1.0174x over previous
#include <cuda_runtime.h>
#include <cuda_fp16.h>

#define NSEQ 12800
#define TSTEPS 512
#define CHUNK_T 4
#define NCHUNK (TSTEPS / CHUNK_T)
#define RING 4
#define ROWB 48                      // padded fp16 x-tile row (bytes)
#define TILE_B (16 * ROWB)           // 768 B per 16x(K) fp16 tile
#define GRS 40                       // gate smem row stride (words): rows land on {0,8,16,24} mod 32
#define GOFF(r) ((((r) >> 2) & 1) * 4)   // row offset: makes 8 producer rows hit 8 distinct bank starts
#define G_B 2560                     // gate buffer bytes (max word 627 < 640)
#define WARP_SMEM (RING * TILE_B + G_B)   // 5632 B per warp

typedef unsigned long long u64;

// ---------- packed f32x2 + fast-math helpers ----------
__device__ __forceinline__ u64 pk2(float lo, float hi) {
    u64 u; asm("mov.b64 %0, {%1,%2};" : "=l"(u) : "f"(lo), "f"(hi)); return u;
}
__device__ __forceinline__ float2 upk2(u64 u) {
    float2 v; asm("mov.b64 {%0,%1}, %2;" : "=f"(v.x), "=f"(v.y) : "l"(u)); return v;
}
__device__ __forceinline__ u64 ffma2(u64 a, u64 b, u64 c) {
    u64 d; asm("fma.rn.f32x2 %0, %1, %2, %3;" : "=l"(d) : "l"(a), "l"(b), "l"(c)); return d;
}
__device__ __forceinline__ float tanh_a(float x) {
    float r; asm("tanh.approx.f32 %0, %1;" : "=f"(r) : "f"(x)); return r;
}
__device__ __forceinline__ float hsum(u64 a) { float2 v = upk2(a); return v.x + v.y; }

// sigmoid(y) = 0.5*tanh(0.5*y) + 0.5 ; the 0.5 factor is pre-folded into the
// r/z weights and biases (both x-side, via MMA B/C fragments, and h-side).
#define KRZ (0.5f)

// ---------- global scratch ----------
// Per-DIRECTION fp16 activation buffers, layout (T, N, 8): a warp's 32 lanes
// store 64 contiguous bytes per step (2 full sectors, no read-modify-write).
__device__ unsigned short g_F0[(size_t)TSTEPS * NSEQ * 8];
__device__ unsigned short g_B0[(size_t)TSTEPS * NSEQ * 8];
__device__ unsigned short g_F1[(size_t)TSTEPS * NSEQ * 8];
__device__ unsigned short g_B1[(size_t)TSTEPS * NSEQ * 8];
__device__ unsigned short g_rawH[(size_t)NSEQ * TSTEPS * 8];

// ---------- raw fp32 -> fp16 convert pre-pass ----------
__global__ void __launch_bounds__(256) cvt_kernel(const float4* __restrict__ in,
                                                  uint2* __restrict__ outp) {
    int i = blockIdx.x * blockDim.x + threadIdx.x;
    float4 v = in[i];
    __half2 h0 = __floats2half2_rn(v.x, v.y);
    __half2 h1 = __floats2half2_rn(v.z, v.w);
    outp[i] = make_uint2(*(unsigned*)&h0, *(unsigned*)&h1);
}

// ---------- per-WARP cp.async x-tile loader ----------
// One 16-row fp16 tile per chunk: row r = (step-in-chunk)*4 + scan.
// Row layout: [fwd-x 8 halves | bwd-x 8 halves] (hsel picks source buffer).
template <int INF, bool L0IN>
__device__ __forceinline__ void issue_chunk(unsigned dst_s,
                                            const __half* __restrict__ xF,
                                            const __half* __restrict__ xB,
                                            int n0, int c, int dir, int lane) {
    int r, hsel; bool pred;
    if (INF == 16) { r = lane >> 1; hsel = lane & 1; pred = true; }
    else           { r = lane & 15; hsel = 0;        pred = lane < 16; }
    int s = c * CHUNK_T + (r >> 2);
    int scan = r & 3;
    int t = dir ? (TSTEPS - 1 - s) : s;
    const __half* g = L0IN
        ? xF + ((size_t)(n0 + scan) * TSTEPS + t) * 8
        : (hsel ? xB : xF) + ((size_t)t * NSEQ + (n0 + scan)) * 8;
    unsigned d = dst_s + r * ROWB + hsel * 16;
    if (pred)
        asm volatile("cp.async.cg.shared.global [%0], [%1], 16;" :: "r"(d), "l"(g));
}

// One bidirectional-GRU layer. Each WARP owns 4 scans of one direction.
// x-projection on TENSOR CORES (mma.m16n8k{16,8}, fp16 in, fp32 accumulate,
// bias in C); D fragments transpose to recurrence lanes via a CONFLICT-FREE
// smem gate buffer (GRS=40 + row offset). h broadcast in fp16 (5 shfl) then
// converted back to fp32 for the recurrence FFMAs. Inter-layer activations
// fp16 in per-direction (T,N,8) buffers. HEAD (layer 3): fwd only, no
// stores; fused 1-step bwd GRU at t=T-1 (h0=0) + lin1/LeakyReLU/lin2 head.
template <int INF, bool L0IN, bool HEAD>
__global__ void __launch_bounds__(128, 4)
gru_layer_kernel(const __half* __restrict__ xF, const __half* __restrict__ xB,
                 __half* __restrict__ outF, __half* __restrict__ outB,
                 const float* __restrict__ Wih, const float* __restrict__ Whh,
                 const float* __restrict__ bih, const float* __restrict__ bhh,
                 int wih_stride,
                 const float* __restrict__ l1w, const float* __restrict__ l1b,
                 const float* __restrict__ l2w, const float* __restrict__ l2b,
                 float* __restrict__ out)
{
    extern __shared__ char sb[];

    const int tid = threadIdx.x;
    const int wid = tid >> 5;
    const int lane = tid & 31;
    const int u = tid & 7;
    const int sg = (tid >> 3) & 3;               // scan within warp
    const int warpG = blockIdx.x * 4 + wid;
    const int dir = HEAD ? 0 : (warpG / (NSEQ / 4));
    const int wi  = HEAD ? warpG : (warpG % (NSEQ / 4));
    const int n0 = wi * 4;
    const int n = n0 + sg;

    char* wsb = sb + wid * WARP_SMEM;            // warp-private region
    char* gsm = wsb + RING * TILE_B;             // gate buffer (fp32)
    const unsigned wsb_s = (unsigned)__cvta_generic_to_shared(wsb);
    float* gw = reinterpret_cast<float*>(gsm);

    const float* wih = Wih + dir * wih_stride;
    const float* whh = Whh + dir * 192;
    const float* bi  = bih + dir * 24;
    const float* bh  = bhh + dir * 24;

    // ---- B fragments (x-projection weights, fp16, pre-scaled) ----
    const int bg = lane >> 2;                    // n-within-tile
    const int bt = lane & 3;                     // k-pair index
    unsigned bfr[6];
#pragma unroll
    for (int j = 0; j < 3; j++) {
        int m = j * 8 + bg;
        float sc = (m < 16) ? KRZ : 1.0f;
        const float* wrow = wih + m * INF + 2 * bt;
        __half2 h0 = __floats2half2_rn(sc * wrow[0], sc * wrow[1]);
        if (INF == 16) {
            __half2 h1 = __floats2half2_rn(sc * wrow[8], sc * wrow[9]);
            bfr[2 * j]     = *(unsigned*)&h0;
            bfr[2 * j + 1] = *(unsigned*)&h1;
        } else {
            bfr[j] = *(unsigned*)&h0;            // k8 path uses bfr[j]
        }
    }
    // C-fragment biases (per-column): r/z cols get 0.5*(bi+bh); n cols bi only.
    float cb0[3], cb1[3];
#pragma unroll
    for (int j = 0; j < 3; j++) {
        int c0 = j * 8 + 2 * bt;
        cb0[j] = (c0     < 16) ? KRZ * (bi[c0]     + bh[c0])     : bi[c0];
        cb1[j] = (c0 + 1 < 16) ? KRZ * (bi[c0 + 1] + bh[c0 + 1]) : bi[c0 + 1];
    }

    // ---- h-recurrence weights (fp32 packed, pre-scaled) ----
    u64 ur[4], uz[4], un[4];
#pragma unroll
    for (int p = 0; p < 4; p++) {
        ur[p] = pk2(KRZ * whh[(u     ) * 8 + 2 * p], KRZ * whh[(u     ) * 8 + 2 * p + 1]);
        uz[p] = pk2(KRZ * whh[(u +  8) * 8 + 2 * p], KRZ * whh[(u +  8) * 8 + 2 * p + 1]);
        un[p] = pk2(       whh[(u + 16) * 8 + 2 * p],        whh[(u + 16) * 8 + 2 * p + 1]);
    }
    const u64 bnhp = pk2(bh[u + 16], 0.0f);

    const int t0 = dir ? (TSTEPS - 1) : 0;
    __half* op = HEAD ? nullptr
                      : ((dir ? outB : outF) + ((size_t)t0 * NSEQ + (size_t)n) * 8 + u);
    const ptrdiff_t ostep = (ptrdiff_t)NSEQ * 8 * (dir ? -1 : 1);

    // ---- prime the x pipeline (3 chunks in flight) ----
    issue_chunk<INF, L0IN>(wsb_s + 0 * TILE_B, xF, xB, n0, 0, dir, lane);
    asm volatile("cp.async.commit_group;" ::: "memory");
    issue_chunk<INF, L0IN>(wsb_s + 1 * TILE_B, xF, xB, n0, 1, dir, lane);
    asm volatile("cp.async.commit_group;" ::: "memory");
    issue_chunk<INF, L0IN>(wsb_s + 2 * TILE_B, xF, xB, n0, 2, dir, lane);
    asm volatile("cp.async.commit_group;" ::: "memory");

    float h = 0.0f;
    const int dg = lane >> 2;                    // D-frag row group
    const int dcol = 2 * (lane & 3);             // D-frag col pair base
    const int dro = GOFF(dg);                    // producer row offset (same for dg, dg+8)

#pragma unroll 1
    for (int c = 0; c < NCHUNK; c++) {
        asm volatile("cp.async.wait_group 2;" ::: "memory");
        __syncwarp();
        const unsigned tile_s = wsb_s + (c & (RING - 1)) * TILE_B;

        // ---- MMA phase: x-projection for 4 steps x 4 scans ----
        unsigned a0, a1, a2, a3;
        if (INF == 16) {
            unsigned la = tile_s + (lane & 15) * ROWB + (lane >> 4) * 16;
            asm volatile("ldmatrix.sync.aligned.m8n8.x4.shared.b16 {%0,%1,%2,%3}, [%4];"
                         : "=r"(a0), "=r"(a1), "=r"(a2), "=r"(a3) : "r"(la));
        } else {
            unsigned la = tile_s + (lane & 15) * ROWB;
            asm volatile("ldmatrix.sync.aligned.m8n8.x2.shared.b16 {%0,%1}, [%2];"
                         : "=r"(a0), "=r"(a1) : "r"(la));
        }
#pragma unroll
        for (int j = 0; j < 3; j++) {
            float d0 = cb0[j], d1 = cb1[j], d2 = cb0[j], d3 = cb1[j];
            if (INF == 16)
                asm("mma.sync.aligned.m16n8k16.row.col.f32.f16.f16.f32 "
                    "{%0,%1,%2,%3}, {%4,%5,%6,%7}, {%8,%9}, {%0,%1,%2,%3};"
                    : "+f"(d0), "+f"(d1), "+f"(d2), "+f"(d3)
                    : "r"(a0), "r"(a1), "r"(a2), "r"(a3),
                      "r"(bfr[2 * j]), "r"(bfr[2 * j + 1]));
            else
                asm("mma.sync.aligned.m16n8k8.row.col.f32.f16.f16.f32 "
                    "{%0,%1,%2,%3}, {%4,%5}, {%6}, {%0,%1,%2,%3};"
                    : "+f"(d0), "+f"(d1), "+f"(d2), "+f"(d3)
                    : "r"(a0), "r"(a1), "r"(bfr[j]));
            int col = j * 8 + dcol;
            *(float2*)(gw + dg * GRS + dro + col)       = make_float2(d0, d1);
            *(float2*)(gw + (dg + 8) * GRS + dro + col) = make_float2(d2, d3);
        }
        __syncwarp();

        // ---- recurrence: 4 steps ----
#pragma unroll
        for (int tt = 0; tt < CHUNK_T; tt++) {
            const int grow = (tt * 4 + sg) * GRS + (tt & 1) * 4;
            float gr = gw[grow + u];             // 0.5*(Wr x + br_i + br_h)
            float gz = gw[grow + 8 + u];
            float gn = gw[grow + 16 + u];        // Wn x + bn_i

            // fp16 h broadcast: pair-up (1 shfl.xor) + gather 4 packed words
            unsigned hb = (unsigned)__half_as_ushort(__float2half_rn(h));
            unsigned pb = __shfl_xor_sync(0xffffffffu, hb, 1);
            unsigned w = (u & 1) ? (pb | (hb << 16)) : (hb | (pb << 16));
            unsigned w0 = __shfl_sync(0xffffffffu, w, 0, 8);
            unsigned w1 = __shfl_sync(0xffffffffu, w, 2, 8);
            unsigned w2 = __shfl_sync(0xffffffffu, w, 4, 8);
            unsigned w3 = __shfl_sync(0xffffffffu, w, 6, 8);
            float2 f0 = __half22float2(*reinterpret_cast<__half2*>(&w0));
            float2 f1 = __half22float2(*reinterpret_cast<__half2*>(&w1));
            float2 f2 = __half22float2(*reinterpret_cast<__half2*>(&w2));
            float2 f3 = __half22float2(*reinterpret_cast<__half2*>(&w3));
            u64 hp[4] = { pk2(f0.x, f0.y), pk2(f1.x, f1.y),
                          pk2(f2.x, f2.y), pk2(f3.x, f3.y) };

            u64 ar = 0ULL, az = 0ULL, ahn = bnhp;
#pragma unroll
            for (int p = 0; p < 4; p++) {
                ar  = ffma2(ur[p], hp[p], ar);
                az  = ffma2(uz[p], hp[p], az);
                ahn = ffma2(un[p], hp[p], ahn);
            }
            float sr = gr + hsum(ar);
            float sz = gz + hsum(az);
            float shn = hsum(ahn);
            float r = fmaf(0.5f, tanh_a(sr), 0.5f);   // sigmoid
            float z = fmaf(0.5f, tanh_a(sz), 0.5f);   // sigmoid
            float nn = tanh_a(fmaf(r, shn, gn));
            h = fmaf(z, h - nn, nn);

            if (!HEAD) { *op = __float2half_rn(h); op += ostep; }
        }

        if (c + 3 < NCHUNK)
            issue_chunk<INF, L0IN>(wsb_s + ((c + 3) & (RING - 1)) * TILE_B,
                                   xF, xB, n0, c + 3, dir, lane);
        asm volatile("cp.async.commit_group;" ::: "memory");
    }

    if (HEAD) {
        // x[T-1] fp16 still resident: last chunk's tile, row 12+sg.
        const __half2* xh = (const __half2*)(wsb + ((NCHUNK - 1) & (RING - 1)) * TILE_B
                                             + (12 + sg) * ROWB);
        u64 xcp[8];
#pragma unroll
        for (int p = 0; p < 8; p++) {
            float2 f = __half22float2(xh[p]);
            xcp[p] = pk2(f.x, f.y);
        }
        // backward-direction single step at t=T-1, h0=0 (gh = b_hh); fp32.
        const float* wihB = Wih + wih_stride;
        const float* biB  = bih + 24;
        const float* bhB  = bhh + 24;
        u64 br2 = pk2(KRZ * (biB[u]     + bhB[u]),     0.0f);
        u64 bz2 = pk2(KRZ * (biB[u + 8] + bhB[u + 8]), 0.0f);
        u64 bx2 = pk2(biB[u + 16], 0.0f);
        const float bnhB = bhB[u + 16];
#pragma unroll
        for (int p = 0; p < 8; p++) {
            u64 wrB = pk2(KRZ * wihB[(u     ) * 16 + 2 * p], KRZ * wihB[(u     ) * 16 + 2 * p + 1]);
            u64 wzB = pk2(KRZ * wihB[(u +  8) * 16 + 2 * p], KRZ * wihB[(u +  8) * 16 + 2 * p + 1]);
            u64 wnB = pk2(       wihB[(u + 16) * 16 + 2 * p],        wihB[(u + 16) * 16 + 2 * p + 1]);
            br2 = ffma2(wrB, xcp[p], br2);
            bz2 = ffma2(wzB, xcp[p], bz2);
            bx2 = ffma2(wnB, xcp[p], bx2);
        }
        float r = fmaf(0.5f, tanh_a(hsum(br2)), 0.5f);
        float z = fmaf(0.5f, tanh_a(hsum(bz2)), 0.5f);
        float nn = tanh_a(fmaf(r, bnhB, hsum(bx2)));
        float hb = (1.0f - z) * nn;   // h0 = 0

        // head: lin1 + LeakyReLU(0.2) + lin2 over [h_f ; h_b]
        float mid = l1b[u];
#pragma unroll
        for (int cc = 0; cc < 8; cc++) {
            float hf_c = __shfl_sync(0xffffffffu, h,  cc, 8);
            float hb_c = __shfl_sync(0xffffffffu, hb, cc, 8);
            mid = fmaf(l1w[u * 16 + cc],     hf_c, mid);
            mid = fmaf(l1w[u * 16 + 8 + cc], hb_c, mid);
        }
        float act = (mid >= 0.0f) ? mid : 0.2f * mid;

        float o = l2b[u];
#pragma unroll
        for (int cc = 0; cc < 8; cc++) {
            float a_c = __shfl_sync(0xffffffffu, act, cc, 8);
            o = fmaf(l2w[u * 8 + cc], a_c, o);
        }
        out[(size_t)n * 8 + u] = o;
    }
}

extern "C" void kernel_launch(void* const* d_in, const int* in_sizes, int n_in,
                              void* d_out, int out_size) {
    (void)in_sizes; (void)n_in; (void)out_size;
    const float* raw  = (const float*)d_in[0];
    const float* Wih0 = (const float*)d_in[1];
    const float* Whh0 = (const float*)d_in[2];
    const float* bih0 = (const float*)d_in[3];
    const float* bhh0 = (const float*)d_in[4];
    const float* WihR = (const float*)d_in[5];   // (3, 2, 24, 16)
    const float* WhhR = (const float*)d_in[6];   // (3, 2, 24, 8)
    const float* bihR = (const float*)d_in[7];   // (3, 2, 24)
    const float* bhhR = (const float*)d_in[8];   // (3, 2, 24)
    const float* l1w  = (const float*)d_in[9];
    const float* l1b  = (const float*)d_in[10];
    const float* l2w  = (const float*)d_in[11];
    const float* l2b  = (const float*)d_in[12];
    float* out = (float*)d_out;

    __half *F0, *B0, *F1, *B1, *rawH;
    cudaGetSymbolAddress((void**)&F0, g_F0);
    cudaGetSymbolAddress((void**)&B0, g_B0);
    cudaGetSymbolAddress((void**)&F1, g_F1);
    cudaGetSymbolAddress((void**)&B1, g_B1);
    cudaGetSymbolAddress((void**)&rawH, g_rawH);

    const int BLK_FULL = 2 * (NSEQ / 16);   // 1600 blocks (fwd + bwd)
    const int BLK_HEAD = NSEQ / 16;         // 800 blocks (fwd only)
    const int SMEM = 4 * WARP_SMEM;         // 22528 B

    // Pre-pass: raw fp32 -> fp16 (N, T, 8)
    cvt_kernel<<<(NSEQ * TSTEPS * 8) / (256 * 4), 256>>>(
        (const float4*)raw, (uint2*)rawH);

    // Layer 0: rawH -> (F0, B0)  (K=8 MMA)
    gru_layer_kernel<8, true, false><<<BLK_FULL, 128, SMEM>>>(
        rawH, rawH, F0, B0, Wih0, Whh0, bih0, bhh0, 192,
        nullptr, nullptr, nullptr, nullptr, nullptr);

    // Layer 1: (F0, B0) -> (F1, B1)
    gru_layer_kernel<16, false, false><<<BLK_FULL, 128, SMEM>>>(
        F0, B0, F1, B1, WihR + 0 * 768, WhhR + 0 * 384, bihR + 0 * 48, bhhR + 0 * 48, 384,
        nullptr, nullptr, nullptr, nullptr, nullptr);

    // Layer 2: (F1, B1) -> (F0, B0)
    gru_layer_kernel<16, false, false><<<BLK_FULL, 128, SMEM>>>(
        F1, B1, F0, B0, WihR + 1 * 768, WhhR + 1 * 384, bihR + 1 * 48, bhhR + 1 * 48, 384,
        nullptr, nullptr, nullptr, nullptr, nullptr);

    // Layer 3 + head: (F0, B0) -> out
    gru_layer_kernel<16, false, true><<<BLK_HEAD, 128, SMEM>>>(
        F0, B0, nullptr, nullptr, WihR + 2 * 768, WhhR + 2 * 384, bihR + 2 * 48, bhhR + 2 * 48, 384,
        l1w, l1b, l2w, l2b, out);
}

// round 17
// speedup vs baseline: 1.1356x; 1.1162x over previous
#include <cuda_runtime.h>
#include <cuda_fp16.h>

#define NSEQ 12800
#define TSTEPS 512
#define CHUNK_T 4
#define NCHUNK (TSTEPS / CHUNK_T)
#define RING 4
#define ROWB 48                      // padded fp16 x-tile row (bytes)
#define TILE_B (16 * ROWB)           // 768 B per 16x(K) fp16 tile
#define GRS 40                       // gate smem row stride (words): rows land on {0,8,16,24} mod 32
#define GOFF(r) ((((r) >> 2) & 1) * 4)   // row offset: 8 producer rows hit 8 distinct bank starts
#define G_B 2560                     // gate buffer bytes
#define WARP_SMEM (RING * TILE_B + G_B)   // 5632 B per warp

typedef unsigned long long u64;

// ---------- packed f32x2 + fast-math helpers ----------
__device__ __forceinline__ u64 pk2(float lo, float hi) {
    u64 u; asm("mov.b64 %0, {%1,%2};" : "=l"(u) : "f"(lo), "f"(hi)); return u;
}
__device__ __forceinline__ float2 upk2(u64 u) {
    float2 v; asm("mov.b64 {%0,%1}, %2;" : "=f"(v.x), "=f"(v.y) : "l"(u)); return v;
}
__device__ __forceinline__ u64 ffma2(u64 a, u64 b, u64 c) {
    u64 d; asm("fma.rn.f32x2 %0, %1, %2, %3;" : "=l"(d) : "l"(a), "l"(b), "l"(c)); return d;
}
__device__ __forceinline__ float tanh_a(float x) {
    float r; asm("tanh.approx.f32 %0, %1;" : "=f"(r) : "f"(x)); return r;
}
__device__ __forceinline__ float hsum(u64 a) { float2 v = upk2(a); return v.x + v.y; }

// sigmoid(y) = 0.5*tanh(0.5*y) + 0.5 ; the 0.5 factor is pre-folded into the
// r/z weights and biases (both x-side, via MMA B/C fragments, and h-side).
#define KRZ (0.5f)

// ---------- global scratch ----------
// Per-DIRECTION fp16 activation buffers, layout (T, N, 8): a warp's 32 lanes
// store 64 contiguous bytes per step (2 full sectors, no read-modify-write).
__device__ unsigned short g_F0[(size_t)TSTEPS * NSEQ * 8];
__device__ unsigned short g_B0[(size_t)TSTEPS * NSEQ * 8];
__device__ unsigned short g_F1[(size_t)TSTEPS * NSEQ * 8];
__device__ unsigned short g_B1[(size_t)TSTEPS * NSEQ * 8];
__device__ unsigned short g_rawH[(size_t)NSEQ * TSTEPS * 8];

// ---------- raw fp32 -> fp16 convert pre-pass ----------
__global__ void __launch_bounds__(256) cvt_kernel(const float4* __restrict__ in,
                                                  uint2* __restrict__ outp) {
    int i = blockIdx.x * blockDim.x + threadIdx.x;
    float4 v = in[i];
    __half2 h0 = __floats2half2_rn(v.x, v.y);
    __half2 h1 = __floats2half2_rn(v.z, v.w);
    outp[i] = make_uint2(*(unsigned*)&h0, *(unsigned*)&h1);
}

// ---------- per-WARP cp.async x-tile loader ----------
// One 16-row fp16 tile per chunk: row r = (step-in-chunk)*4 + scan.
// Row layout: [fwd-x 8 halves | bwd-x 8 halves] (hsel picks source buffer).
template <int INF, bool L0IN>
__device__ __forceinline__ void issue_chunk(unsigned dst_s,
                                            const __half* __restrict__ xF,
                                            const __half* __restrict__ xB,
                                            int n0, int c, int dir, int lane) {
    int r, hsel; bool pred;
    if (INF == 16) { r = lane >> 1; hsel = lane & 1; pred = true; }
    else           { r = lane & 15; hsel = 0;        pred = lane < 16; }
    int s = c * CHUNK_T + (r >> 2);
    int scan = r & 3;
    int t = dir ? (TSTEPS - 1 - s) : s;
    const __half* g = L0IN
        ? xF + ((size_t)(n0 + scan) * TSTEPS + t) * 8
        : (hsel ? xB : xF) + ((size_t)t * NSEQ + (n0 + scan)) * 8;
    unsigned d = dst_s + r * ROWB + hsel * 16;
    if (pred)
        asm volatile("cp.async.cg.shared.global [%0], [%1], 16;" :: "r"(d), "l"(g));
}

// One bidirectional-GRU layer. Each WARP owns 4 scans of one direction.
// x-projection on TENSOR CORES (mma.m16n8k{16,8}, fp16 in, fp32 accumulate,
// bias in C); D fragments transpose to recurrence lanes via a CONFLICT-FREE
// smem gate buffer (GRS=40 + row offset). h broadcast in fp32 via 8 shfl
// (minimal issue count; L1 has headroom). Inter-layer activations fp16 in
// per-direction (T,N,8) buffers. HEAD (layer 3): fwd only, no stores; fused
// 1-step bwd GRU at t=T-1 (h0=0) + lin1/LeakyReLU(0.2)/lin2 head.
template <int INF, bool L0IN, bool HEAD>
__global__ void __launch_bounds__(128, 4)
gru_layer_kernel(const __half* __restrict__ xF, const __half* __restrict__ xB,
                 __half* __restrict__ outF, __half* __restrict__ outB,
                 const float* __restrict__ Wih, const float* __restrict__ Whh,
                 const float* __restrict__ bih, const float* __restrict__ bhh,
                 int wih_stride,
                 const float* __restrict__ l1w, const float* __restrict__ l1b,
                 const float* __restrict__ l2w, const float* __restrict__ l2b,
                 float* __restrict__ out)
{
    extern __shared__ char sb[];

    const int tid = threadIdx.x;
    const int wid = tid >> 5;
    const int lane = tid & 31;
    const int u = tid & 7;
    const int sg = (tid >> 3) & 3;               // scan within warp
    const int warpG = blockIdx.x * 4 + wid;
    const int dir = HEAD ? 0 : (warpG / (NSEQ / 4));
    const int wi  = HEAD ? warpG : (warpG % (NSEQ / 4));
    const int n0 = wi * 4;
    const int n = n0 + sg;

    char* wsb = sb + wid * WARP_SMEM;            // warp-private region
    char* gsm = wsb + RING * TILE_B;             // gate buffer (fp32)
    const unsigned wsb_s = (unsigned)__cvta_generic_to_shared(wsb);
    float* gw = reinterpret_cast<float*>(gsm);

    const float* wih = Wih + dir * wih_stride;
    const float* whh = Whh + dir * 192;
    const float* bi  = bih + dir * 24;
    const float* bh  = bhh + dir * 24;

    // ---- B fragments (x-projection weights, fp16, pre-scaled) ----
    const int bg = lane >> 2;                    // n-within-tile
    const int bt = lane & 3;                     // k-pair index
    unsigned bfr[6];
#pragma unroll
    for (int j = 0; j < 3; j++) {
        int m = j * 8 + bg;
        float sc = (m < 16) ? KRZ : 1.0f;
        const float* wrow = wih + m * INF + 2 * bt;
        __half2 h0 = __floats2half2_rn(sc * wrow[0], sc * wrow[1]);
        if (INF == 16) {
            __half2 h1 = __floats2half2_rn(sc * wrow[8], sc * wrow[9]);
            bfr[2 * j]     = *(unsigned*)&h0;
            bfr[2 * j + 1] = *(unsigned*)&h1;
        } else {
            bfr[j] = *(unsigned*)&h0;            // k8 path uses bfr[j]
        }
    }
    // C-fragment biases (per-column): r/z cols get 0.5*(bi+bh); n cols bi only.
    float cb0[3], cb1[3];
#pragma unroll
    for (int j = 0; j < 3; j++) {
        int c0 = j * 8 + 2 * bt;
        cb0[j] = (c0     < 16) ? KRZ * (bi[c0]     + bh[c0])     : bi[c0];
        cb1[j] = (c0 + 1 < 16) ? KRZ * (bi[c0 + 1] + bh[c0 + 1]) : bi[c0 + 1];
    }

    // ---- h-recurrence weights (fp32 packed, pre-scaled) ----
    u64 ur[4], uz[4], un[4];
#pragma unroll
    for (int p = 0; p < 4; p++) {
        ur[p] = pk2(KRZ * whh[(u     ) * 8 + 2 * p], KRZ * whh[(u     ) * 8 + 2 * p + 1]);
        uz[p] = pk2(KRZ * whh[(u +  8) * 8 + 2 * p], KRZ * whh[(u +  8) * 8 + 2 * p + 1]);
        un[p] = pk2(       whh[(u + 16) * 8 + 2 * p],        whh[(u + 16) * 8 + 2 * p + 1]);
    }
    const u64 bnhp = pk2(bh[u + 16], 0.0f);

    const int t0 = dir ? (TSTEPS - 1) : 0;
    __half* op = HEAD ? nullptr
                      : ((dir ? outB : outF) + ((size_t)t0 * NSEQ + (size_t)n) * 8 + u);
    const ptrdiff_t ostep = (ptrdiff_t)NSEQ * 8 * (dir ? -1 : 1);

    // ---- prime the x pipeline (3 chunks in flight) ----
    issue_chunk<INF, L0IN>(wsb_s + 0 * TILE_B, xF, xB, n0, 0, dir, lane);
    asm volatile("cp.async.commit_group;" ::: "memory");
    issue_chunk<INF, L0IN>(wsb_s + 1 * TILE_B, xF, xB, n0, 1, dir, lane);
    asm volatile("cp.async.commit_group;" ::: "memory");
    issue_chunk<INF, L0IN>(wsb_s + 2 * TILE_B, xF, xB, n0, 2, dir, lane);
    asm volatile("cp.async.commit_group;" ::: "memory");

    float h = 0.0f;
    const int dg = lane >> 2;                    // D-frag row group
    const int dcol = 2 * (lane & 3);             // D-frag col pair base
    const int dro = GOFF(dg);                    // producer row offset (same for dg, dg+8)

#pragma unroll 1
    for (int c = 0; c < NCHUNK; c++) {
        asm volatile("cp.async.wait_group 2;" ::: "memory");
        __syncwarp();
        const unsigned tile_s = wsb_s + (c & (RING - 1)) * TILE_B;

        // ---- MMA phase: x-projection for 4 steps x 4 scans ----
        unsigned a0, a1, a2, a3;
        if (INF == 16) {
            unsigned la = tile_s + (lane & 15) * ROWB + (lane >> 4) * 16;
            asm volatile("ldmatrix.sync.aligned.m8n8.x4.shared.b16 {%0,%1,%2,%3}, [%4];"
                         : "=r"(a0), "=r"(a1), "=r"(a2), "=r"(a3) : "r"(la));
        } else {
            unsigned la = tile_s + (lane & 15) * ROWB;
            asm volatile("ldmatrix.sync.aligned.m8n8.x2.shared.b16 {%0,%1}, [%2];"
                         : "=r"(a0), "=r"(a1) : "r"(la));
        }
#pragma unroll
        for (int j = 0; j < 3; j++) {
            float d0 = cb0[j], d1 = cb1[j], d2 = cb0[j], d3 = cb1[j];
            if (INF == 16)
                asm("mma.sync.aligned.m16n8k16.row.col.f32.f16.f16.f32 "
                    "{%0,%1,%2,%3}, {%4,%5,%6,%7}, {%8,%9}, {%0,%1,%2,%3};"
                    : "+f"(d0), "+f"(d1), "+f"(d2), "+f"(d3)
                    : "r"(a0), "r"(a1), "r"(a2), "r"(a3),
                      "r"(bfr[2 * j]), "r"(bfr[2 * j + 1]));
            else
                asm("mma.sync.aligned.m16n8k8.row.col.f32.f16.f16.f32 "
                    "{%0,%1,%2,%3}, {%4,%5}, {%6}, {%0,%1,%2,%3};"
                    : "+f"(d0), "+f"(d1), "+f"(d2), "+f"(d3)
                    : "r"(a0), "r"(a1), "r"(bfr[j]));
            int col = j * 8 + dcol;
            *(float2*)(gw + dg * GRS + dro + col)       = make_float2(d0, d1);
            *(float2*)(gw + (dg + 8) * GRS + dro + col) = make_float2(d2, d3);
        }
        __syncwarp();

        // ---- recurrence: 4 steps ----
#pragma unroll
        for (int tt = 0; tt < CHUNK_T; tt++) {
            const int grow = (tt * 4 + sg) * GRS + (tt & 1) * 4;
            float gr = gw[grow + u];             // 0.5*(Wr x + br_i + br_h)
            float gz = gw[grow + 8 + u];
            float gn = gw[grow + 16 + u];        // Wn x + bn_i

            // fp32 h broadcast (8 shfl; minimal issue count)
            u64 hp[4];
#pragma unroll
            for (int p = 0; p < 4; p++) {
                float lo = __shfl_sync(0xffffffffu, h, 2 * p,     8);
                float hi = __shfl_sync(0xffffffffu, h, 2 * p + 1, 8);
                hp[p] = pk2(lo, hi);
            }
            // seed accumulators with the gate values (folds the final adds)
            u64 ar = pk2(gr, 0.0f), az = pk2(gz, 0.0f), ahn = bnhp;
#pragma unroll
            for (int p = 0; p < 4; p++) {
                ar  = ffma2(ur[p], hp[p], ar);
                az  = ffma2(uz[p], hp[p], az);
                ahn = ffma2(un[p], hp[p], ahn);
            }
            float sr = hsum(ar);
            float sz = hsum(az);
            float shn = hsum(ahn);
            float r = fmaf(0.5f, tanh_a(sr), 0.5f);   // sigmoid
            float z = fmaf(0.5f, tanh_a(sz), 0.5f);   // sigmoid
            float nn = tanh_a(fmaf(r, shn, gn));
            h = fmaf(z, h - nn, nn);

            if (!HEAD) { *op = __float2half_rn(h); op += ostep; }
        }

        if (c + 3 < NCHUNK)
            issue_chunk<INF, L0IN>(wsb_s + ((c + 3) & (RING - 1)) * TILE_B,
                                   xF, xB, n0, c + 3, dir, lane);
        asm volatile("cp.async.commit_group;" ::: "memory");
    }

    if (HEAD) {
        // x[T-1] fp16 still resident: last chunk's tile, row 12+sg.
        const __half2* xh = (const __half2*)(wsb + ((NCHUNK - 1) & (RING - 1)) * TILE_B
                                             + (12 + sg) * ROWB);
        u64 xcp[8];
#pragma unroll
        for (int p = 0; p < 8; p++) {
            float2 f = __half22float2(xh[p]);
            xcp[p] = pk2(f.x, f.y);
        }
        // backward-direction single step at t=T-1, h0=0 (gh = b_hh); fp32.
        const float* wihB = Wih + wih_stride;
        const float* biB  = bih + 24;
        const float* bhB  = bhh + 24;
        u64 br2 = pk2(KRZ * (biB[u]     + bhB[u]),     0.0f);
        u64 bz2 = pk2(KRZ * (biB[u + 8] + bhB[u + 8]), 0.0f);
        u64 bx2 = pk2(biB[u + 16], 0.0f);
        const float bnhB = bhB[u + 16];
#pragma unroll
        for (int p = 0; p < 8; p++) {
            u64 wrB = pk2(KRZ * wihB[(u     ) * 16 + 2 * p], KRZ * wihB[(u     ) * 16 + 2 * p + 1]);
            u64 wzB = pk2(KRZ * wihB[(u +  8) * 16 + 2 * p], KRZ * wihB[(u +  8) * 16 + 2 * p + 1]);
            u64 wnB = pk2(       wihB[(u + 16) * 16 + 2 * p],        wihB[(u + 16) * 16 + 2 * p + 1]);
            br2 = ffma2(wrB, xcp[p], br2);
            bz2 = ffma2(wzB, xcp[p], bz2);
            bx2 = ffma2(wnB, xcp[p], bx2);
        }
        float r = fmaf(0.5f, tanh_a(hsum(br2)), 0.5f);
        float z = fmaf(0.5f, tanh_a(hsum(bz2)), 0.5f);
        float nn = tanh_a(fmaf(r, bnhB, hsum(bx2)));
        float hb = (1.0f - z) * nn;   // h0 = 0

        // head: lin1 + LeakyReLU(0.2) + lin2 over [h_f ; h_b]
        float mid = l1b[u];
#pragma unroll
        for (int cc = 0; cc < 8; cc++) {
            float hf_c = __shfl_sync(0xffffffffu, h,  cc, 8);
            float hb_c = __shfl_sync(0xffffffffu, hb, cc, 8);
            mid = fmaf(l1w[u * 16 + cc],     hf_c, mid);
            mid = fmaf(l1w[u * 16 + 8 + cc], hb_c, mid);
        }
        float act = (mid >= 0.0f) ? mid : 0.2f * mid;

        float o = l2b[u];
#pragma unroll
        for (int cc = 0; cc < 8; cc++) {
            float a_c = __shfl_sync(0xffffffffu, act, cc, 8);
            o = fmaf(l2w[u * 8 + cc], a_c, o);
        }
        out[(size_t)n * 8 + u] = o;
    }
}

extern "C" void kernel_launch(void* const* d_in, const int* in_sizes, int n_in,
                              void* d_out, int out_size) {
    (void)in_sizes; (void)n_in; (void)out_size;
    const float* raw  = (const float*)d_in[0];
    const float* Wih0 = (const float*)d_in[1];
    const float* Whh0 = (const float*)d_in[2];
    const float* bih0 = (const float*)d_in[3];
    const float* bhh0 = (const float*)d_in[4];
    const float* WihR = (const float*)d_in[5];   // (3, 2, 24, 16)
    const float* WhhR = (const float*)d_in[6];   // (3, 2, 24, 8)
    const float* bihR = (const float*)d_in[7];   // (3, 2, 24)
    const float* bhhR = (const float*)d_in[8];   // (3, 2, 24)
    const float* l1w  = (const float*)d_in[9];
    const float* l1b  = (const float*)d_in[10];
    const float* l2w  = (const float*)d_in[11];
    const float* l2b  = (const float*)d_in[12];
    float* out = (float*)d_out;

    __half *F0, *B0, *F1, *B1, *rawH;
    cudaGetSymbolAddress((void**)&F0, g_F0);
    cudaGetSymbolAddress((void**)&B0, g_B0);
    cudaGetSymbolAddress((void**)&F1, g_F1);
    cudaGetSymbolAddress((void**)&B1, g_B1);
    cudaGetSymbolAddress((void**)&rawH, g_rawH);

    const int BLK_FULL = 2 * (NSEQ / 16);   // 1600 blocks (fwd + bwd)
    const int BLK_HEAD = NSEQ / 16;         // 800 blocks (fwd only)
    const int SMEM = 4 * WARP_SMEM;         // 22528 B

    // Pre-pass: raw fp32 -> fp16 (N, T, 8)
    cvt_kernel<<<(NSEQ * TSTEPS * 8) / (256 * 4), 256>>>(
        (const float4*)raw, (uint2*)rawH);

    // Layer 0: rawH -> (F0, B0)  (K=8 MMA)
    gru_layer_kernel<8, true, false><<<BLK_FULL, 128, SMEM>>>(
        rawH, rawH, F0, B0, Wih0, Whh0, bih0, bhh0, 192,
        nullptr, nullptr, nullptr, nullptr, nullptr);

    // Layer 1: (F0, B0) -> (F1, B1)
    gru_layer_kernel<16, false, false><<<BLK_FULL, 128, SMEM>>>(
        F0, B0, F1, B1, WihR + 0 * 768, WhhR + 0 * 384, bihR + 0 * 48, bhhR + 0 * 48, 384,
        nullptr, nullptr, nullptr, nullptr, nullptr);

    // Layer 2: (F1, B1) -> (F0, B0)
    gru_layer_kernel<16, false, false><<<BLK_FULL, 128, SMEM>>>(
        F1, B1, F0, B0, WihR + 1 * 768, WhhR + 1 * 384, bihR + 1 * 48, bhhR + 1 * 48, 384,
        nullptr, nullptr, nullptr, nullptr, nullptr);

    // Layer 3 + head: (F0, B0) -> out
    gru_layer_kernel<16, false, true><<<BLK_HEAD, 128, SMEM>>>(
        F0, B0, nullptr, nullptr, WihR + 2 * 768, WhhR + 2 * 384, bihR + 2 * 48, bhhR + 2 * 48, 384,
        l1w, l1b, l2w, l2b, out);
}